// round 9
// baseline (speedup 1.0000x reference)
#include <cuda_runtime.h>

// Problem constants
#define BB 8
#define CC 32
#define DD 32
#define TT 32
#define HH 96
#define WW 96
#define MT 8
#define MS 16
#define BC (BB*CC)        // 256
#define BD (BB*DD)        // 256
#define HW (HH*WW)        // 9216
#define NMODE (MT*MS*MS)  // 2048
#define NROW (BC*MT*MS)   // 32768 rows of F2
#define TWO_PI 6.28318530717958647692f

// Y/Z smem row stride (floats). 144: h-parity offsets banks by 16 -> every
// phase's LDS/STS pattern is conflict-free. smem = 2*96*144*4 = 110592 B -> 2 CTAs/SM.
#define ZSTR 144
#define SMEM_BYTES (2*HH*ZSTR*4)

// ---------------- scratch (static device globals; no allocation) ----------------
__device__ float g_F2r[WW*NROW];         // after T+H DFT, W-MAJOR: (w, bc*128+kt*16+kx)
__device__ float g_F2i[WW*NROW];
__device__ float g_F3r[BC*NMODE];        // after W-DFT: (bc, m)  m = kt*256+kx*16+ky
__device__ float g_F3i[BC*NMODE];
__device__ float g_Sr [BD*NMODE];        // after mix:   (bd, m)
__device__ float g_Si [BD*NMODE];

// ---------------- compile-time trig (Taylor, double precision) ----------------
__host__ __device__ constexpr double ct_cos(double x) {
    double x2 = x * x, t = 1.0, s = 1.0;
    for (int k = 1; k <= 26; k++) { t *= -x2 / ((2.0*k - 1.0) * (2.0*k)); s += t; }
    return s;
}
__host__ __device__ constexpr double ct_sin(double x) {
    double x2 = x * x, t = x, s = x;
    for (int k = 1; k <= 26; k++) { t *= -x2 / ((2.0*k) * (2.0*k + 1.0)); s += t; }
    return s;
}

// Twiddle cos/sin(2*pi*P/N) with exact 0 / +-1 at quadrant points
template<int P, int N> struct TW {
    static constexpr int    q0 = ((P % N) + N) % N;
    static constexpr int    aq = (q0 > N - q0) ? (N - q0) : q0;
    static constexpr int    ss = (q0 > N/2) ? -1 : 1;
    static constexpr bool c_zero = (4*aq == N);
    static constexpr bool s_zero = (aq == 0) || (2*aq == N);
    static constexpr float c =
        (aq == 0)     ? 1.0f  :
        (2*aq == N)   ? -1.0f :
        c_zero        ? 0.0f  :
        (float)ct_cos(6.283185307179586476925286766559 * (double)aq / (double)N);
    static constexpr float s =
        s_zero        ? 0.0f :
        (4*aq == N)   ? (ss > 0 ? 1.0f : -1.0f) :
        (float)(ss * ct_sin(6.283185307179586476925286766559 * (double)aq / (double)N));
};

template<int P, int N, int SG = 1>
__device__ __forceinline__ float fC(float v, float acc) {
    using T = TW<P, N>;
    constexpr float cc = (SG < 0) ? -T::c : T::c;
    if constexpr (T::c_zero)         return acc;
    else if constexpr (cc ==  1.0f)  return acc + v;
    else if constexpr (cc == -1.0f)  return acc - v;
    else                             return fmaf(v, cc, acc);
}
template<int P, int N, int SG = 1>
__device__ __forceinline__ float fS(float v, float acc) {
    using T = TW<P, N>;
    constexpr float sv = (SG < 0) ? -T::s : T::s;
    if constexpr (T::s_zero)         return acc;
    else if constexpr (sv ==  1.0f)  return acc + v;
    else if constexpr (sv == -1.0f)  return acc - v;
    else                             return fmaf(v, sv, acc);
}

// ---------------- compile-time unroller ----------------
template<int I> struct Ic { static constexpr int v = I; };
template<int I, int E, class F> __device__ __forceinline__ void UNR(F&& f) {
    if constexpr (I < E) { f(Ic<I>{}); UNR<I+1, E>(f); }
}

// ---------------- KA: fused T-DFT + H-DFT  (x -> F2, w-major), w-tile 16, 256 thr ----------------
// smem Y layout: [h][kt*16 + wl], row stride ZSTR
__global__ void __launch_bounds__(256) kA_fwd(const float* __restrict__ x) {
    extern __shared__ float sm[];
    float* Yr = sm;                     // HH*ZSTR floats
    float* Yi = sm + HH*ZSTR;
    const int tid = threadIdx.x;
    const int bc = blockIdx.x / 6;
    const int w0 = (blockIdx.x % 6) * 16;
    const float* xb = x + (size_t)bc * TT * HW + w0;

    const int wl = tid & 15;

    // phase1: T-DFT (real -> complex), folded over t <-> 32-t. 16 hs x 6 passes.
    {
        const int hs = tid >> 4;            // 0..15
        for (int p = 0; p < 6; p++) {
            const int h = p * 16 + hs;
            const float* xp = xb + h * WW + wl;
            float ar[MT], ai[MT];
            float x0  = xp[0];
            float x16 = xp[16 * HW];
            UNR<0,MT>([&](auto K){ constexpr int k = decltype(K)::v;
                ar[k] = (k & 1) ? (x0 - x16) : (x0 + x16);
                ai[k] = 0.0f; });
            UNR<1,16>([&](auto T){ constexpr int t = decltype(T)::v;
                float a = xp[(size_t)t * HW];
                float b = xp[(size_t)(TT - t) * HW];
                float pt = a + b, mt = a - b;
                UNR<0,MT>([&](auto K){ constexpr int k = decltype(K)::v;
                    ar[k] = fC<t*k, TT>(pt, ar[k]);
                    ai[k] = fS<t*k, TT, -1>(mt, ai[k]);
                });
            });
            UNR<0,MT>([&](auto K){ constexpr int k = decltype(K)::v;
                Yr[h*ZSTR + k*16 + wl] = ar[k];
                Yi[h*ZSTR + k*16 + wl] = ai[k]; });
        }
    }
    __syncthreads();

    // phase2: H-DFT (complex), folded over h <-> 96-h. kx split in two halves.
    {
        const int kt   = (tid >> 4) & 7;
        const int half = tid >> 7;
        const float* yr = Yr + kt*16 + wl;
        const float* yi = Yi + kt*16 + wl;
        auto run = [&](auto K0C){
            constexpr int K0 = decltype(K0C)::v;
            float fr[8], fi[8];
            float a0  = yr[0],       b0  = yi[0];
            float a48 = yr[48*ZSTR], b48 = yi[48*ZSTR];
            UNR<0,8>([&](auto J){ constexpr int j = decltype(J)::v; constexpr int kx = K0 + j;
                fr[j] = (kx & 1) ? (a0 - a48) : (a0 + a48);
                fi[j] = (kx & 1) ? (b0 - b48) : (b0 + b48); });
            UNR<1,48>([&](auto H){ constexpr int h = decltype(H)::v;
                float a  = yr[h*ZSTR],      b  = yi[h*ZSTR];
                float a2 = yr[(96-h)*ZSTR], b2 = yi[(96-h)*ZSTR];
                float pa = a + a2, ma = a - a2, pb = b + b2, mb = b - b2;
                UNR<0,8>([&](auto J){ constexpr int j = decltype(J)::v; constexpr int kx = K0 + j;
                    fr[j] = fC<h*kx, HH>(pa, fS<h*kx, HH>(mb, fr[j]));
                    fi[j] = fC<h*kx, HH>(pb, fS<h*kx, HH, -1>(ma, fi[j]));
                });
            });
            size_t base = (size_t)(w0 + wl) * NROW + bc*128 + kt*16 + K0;
            UNR<0,8>([&](auto J){ constexpr int j = decltype(J)::v;
                g_F2r[base + j] = fr[j];
                g_F2i[base + j] = fi[j]; });
        };
        if (half == 0) run(Ic<0>{}); else run(Ic<8>{});
    }
}

// ---------------- K3: W-DFT (F2 -> F3), coalesced, folded over w <-> 96-w ----------------
__global__ void __launch_bounds__(128) k3_wdft() {
    int r = blockIdx.x * 128 + threadIdx.x;       // 32768 rows, exact
    const float* pr = g_F2r + r;
    const float* pi = g_F2i + r;
    float fr[MS], fi[MS];
    {
        float a0  = pr[0],                  b0  = pi[0];
        float a48 = pr[(size_t)48 * NROW],  b48 = pi[(size_t)48 * NROW];
        UNR<0,MS>([&](auto K){ constexpr int ky = decltype(K)::v;
            fr[ky] = (ky & 1) ? (a0 - a48) : (a0 + a48);
            fi[ky] = (ky & 1) ? (b0 - b48) : (b0 + b48); });
    }
    UNR<1,48>([&](auto WI){ constexpr int w = decltype(WI)::v;
        float a  = pr[(size_t)w * NROW],      b  = pi[(size_t)w * NROW];
        float a2 = pr[(size_t)(96-w) * NROW], b2 = pi[(size_t)(96-w) * NROW];
        float pa = a + a2, ma = a - a2, pb = b + b2, mb = b - b2;
        UNR<0,MS>([&](auto K){ constexpr int ky = decltype(K)::v;
            fr[ky] = fC<w*ky, WW>(pa, fS<w*ky, WW>(mb, fr[ky]));
            fi[ky] = fC<w*ky, WW>(pb, fS<w*ky, WW, -1>(ma, fi[ky]));
        });
    });
    size_t o = (size_t)r * MS;
    UNR<0,MS>([&](auto K){ constexpr int ky = decltype(K)::v;
        g_F3r[o + ky] = fr[ky];
        g_F3i[o + ky] = fi[ky]; });
}

// ---------------- K4: channel mix, weights read in ORIGINAL layout ----------------
__global__ void __launch_bounds__(256) k4_mix(const float* __restrict__ wr,
                                              const float* __restrict__ wi) {
    __shared__ float Xr[BC*8], Xi[BC*8];         // 16 KB
    const int m0 = blockIdx.x * 8;
    const int tid = threadIdx.x;
    for (int i = tid; i < BC*8; i += 256) {
        int bcc = i >> 3, mm = i & 7;
        Xr[i] = g_F3r[(size_t)bcc * NMODE + m0 + mm];
        Xi[i] = g_F3i[(size_t)bcc * NMODE + m0 + mm];
    }
    __syncthreads();
    const int d  = tid >> 3;
    const int ml = tid & 7;
    const int m  = m0 + ml;

    float sr[BB], si[BB];
#pragma unroll
    for (int b = 0; b < BB; b++) { sr[b] = 0.0f; si[b] = 0.0f; }

#pragma unroll 4
    for (int c = 0; c < CC; c++) {
        float a  = wr[(size_t)(c*DD + d) * NMODE + m];
        float bb = wi[(size_t)(c*DD + d) * NMODE + m];
#pragma unroll
        for (int b = 0; b < BB; b++) {
            float xr = Xr[(b*CC + c)*8 + ml];
            float xi = Xi[(b*CC + c)*8 + ml];
            sr[b] = fmaf(xr, a,  fmaf(-xi, bb, sr[b]));
            si[b] = fmaf(xr, bb, fmaf( xi, a,  si[b]));
        }
    }
    float sc = (((m & (MS-1)) == 0) ? 1.0f : 2.0f) * (1.0f / 294912.0f);
#pragma unroll
    for (int b = 0; b < BB; b++) {
        size_t o = (size_t)(b*DD + d) * NMODE + m;
        g_Sr[o] = sr[b] * sc;
        g_Si[o] = si[b] * sc;
    }
}

// ---------------- KB: fused W-exp + H-exp + T-exp  (S -> out), w-tile 16, 256 thr ----------------
// phase0 keeps a1[16] in registers (redundant across halves) -> no a1 smem, one less sync.
// smem: Z only = 2*HH*ZSTR floats = 110592 B -> 2 CTAs/SM.
__global__ void __launch_bounds__(256) kB_inv(float* __restrict__ out) {
    extern __shared__ float sm[];
    float* Zr  = sm;                             // HH*ZSTR floats
    float* Zi  = sm + HH*ZSTR;
    float*  Ssr = sm;                            // phase0 staging aliases Z
    float*  Ssi = sm + 2048;
    float2* tab = reinterpret_cast<float2*>(sm + 4096);   // [ky][wl] 256 float2

    const int tid = threadIdx.x;
    const int bd = blockIdx.x / 6;
    const int w0 = (blockIdx.x % 6) * 16;
    const int wl = tid & 15;
    const int kt = (tid >> 4) & 7;
    const int half = tid >> 7;

    {   // load S tile (coalesced) + per-block w table
        const float* srp = g_Sr + (size_t)bd * NMODE;
        const float* sip = g_Si + (size_t)bd * NMODE;
        for (int i = tid; i < NMODE; i += 256) { Ssr[i] = srp[i]; Ssi[i] = sip[i]; }
        {
            int ky = tid >> 4, wl2 = tid & 15;
            float ssin, ccos;
            sincosf(TWO_PI * (float)((ky * (w0 + wl2)) % WW) / (float)WW, &ssin, &ccos);
            tab[tid] = make_float2(ccos, ssin);
        }
    }
    __syncthreads();

    // phase0: W-expand into registers, all 16 kx per thread, e^{+i 2pi ky w / 96}
    float a1r[MS], a1i[MS];
    {
        float ec[MS], es[MS];
#pragma unroll
        for (int ky = 0; ky < MS; ky++) { float2 e = tab[ky*16 + wl]; ec[ky] = e.x; es[ky] = e.y; }
#pragma unroll
        for (int kx = 0; kx < MS; kx++) {
            const float* pr = Ssr + (kt*MS + kx) * MS;
            const float* pi = Ssi + (kt*MS + kx) * MS;
            float rr = 0.f, ii = 0.f;
#pragma unroll
            for (int ky = 0; ky < MS; ky++) {
                float sv = pr[ky], iv = pi[ky];
                rr = fmaf(sv, ec[ky], fmaf(-iv, es[ky], rr));
                ii = fmaf(sv, es[ky], fmaf( iv, ec[ky], ii));
            }
            a1r[kx] = rr; a1i[kx] = ii;
        }
    }
    __syncthreads();   // staging reads done before Z overwrites

    // phase1: H-expand, folded over output h <-> 96-h; halves split the h range
    {
        auto body = [&](auto H){ constexpr int h = decltype(H)::v;
            float C = 0.f, S = 0.f, C2 = 0.f, S2 = 0.f;
            UNR<0,MS>([&](auto KX){ constexpr int kx = decltype(KX)::v;
                C  = fC<kx*h, HH>(a1r[kx], C);
                C2 = fC<kx*h, HH>(a1i[kx], C2);
                S  = fS<kx*h, HH>(a1i[kx], S);
                S2 = fS<kx*h, HH>(a1r[kx], S2);
            });
            Zr[h*ZSTR + kt*16 + wl] = C - S;
            Zi[h*ZSTR + kt*16 + wl] = C2 + S2;
            if constexpr (h >= 1 && h <= 47) {
                Zr[(96-h)*ZSTR + kt*16 + wl] = C + S;
                Zi[(96-h)*ZSTR + kt*16 + wl] = C2 - S2;
            }
        };
        if (half == 0) UNR<0,25>(body); else UNR<25,49>(body);
    }
    __syncthreads();

    // phase2: T-expand + real part, folded over output t <-> 32-t. 16 hs x 6 passes.
    float* ob = out + (size_t)bd * TT * HW + w0;
    const int hs = tid >> 4;            // 0..15
    for (int p = 0; p < 6; p++) {
        const int h = p * 16 + hs;
        float zr[MT], zi[MT];
        UNR<0,MT>([&](auto K){ constexpr int k = decltype(K)::v;
            zr[k] = Zr[h*ZSTR + k*16 + wl];
            zi[k] = Zi[h*ZSTR + k*16 + wl]; });
        float* op = ob + h * WW + wl;
        {   // t = 0 and t = 16
            float s0 = 0.f, s16 = 0.f;
            UNR<0,MT>([&](auto K){ constexpr int k = decltype(K)::v;
                s0 += zr[k];
                s16 = (k & 1) ? (s16 - zr[k]) : (s16 + zr[k]); });
            op[0] = s0;
            op[(size_t)16 * HW] = s16;
        }
        UNR<1,16>([&](auto T){ constexpr int t = decltype(T)::v;
            float C = 0.f, S = 0.f;
            UNR<0,MT>([&](auto K){ constexpr int k = decltype(K)::v;
                C = fC<k*t, TT>(zr[k], C);
                S = fS<k*t, TT>(zi[k], S);
            });
            op[(size_t)t * HW]        = C - S;
            op[(size_t)(32 - t) * HW] = C + S;
        });
    }
}

// ---------------- launch ----------------
extern "C" void kernel_launch(void* const* d_in, const int* in_sizes, int n_in,
                              void* d_out, int out_size) {
    (void)in_sizes; (void)n_in; (void)out_size;
    const float* x  = (const float*)d_in[0];
    const float* wr = (const float*)d_in[1];
    const float* wi = (const float*)d_in[2];
    float* out = (float*)d_out;

    cudaFuncSetAttribute(kA_fwd, cudaFuncAttributeMaxDynamicSharedMemorySize, SMEM_BYTES);
    cudaFuncSetAttribute(kB_inv, cudaFuncAttributeMaxDynamicSharedMemorySize, SMEM_BYTES);

    kA_fwd <<<1536, 256, SMEM_BYTES>>>(x);    // 256 bc * 6 w-groups
    k3_wdft<<<256,  128>>>();                 // 32768 rows
    k4_mix <<<256,  256>>>(wr, wi);           // 2048 modes / 8 per block
    kB_inv <<<1536, 256, SMEM_BYTES>>>(out);  // 256 bd * 6 w-groups
}

// round 10
// speedup vs baseline: 1.1569x; 1.1569x over previous
#include <cuda_runtime.h>

// Problem constants
#define BB 8
#define CC 32
#define DD 32
#define TT 32
#define HH 96
#define WW 96
#define MT 8
#define MS 16
#define BC (BB*CC)        // 256
#define BD (BB*DD)        // 256
#define HW (HH*WW)        // 9216
#define NMODE (MT*MS*MS)  // 2048
#define NROW (BC*MT*MS)   // 32768 rows of F2
#define TWO_PI 6.28318530717958647692f

// Y/Z smem row stride (floats). 144: h-parity offsets banks by 16 -> every
// phase's LDS/STS pattern is conflict-free. smem = 2*96*144*4 = 110592 B -> 2 CTAs/SM.
#define ZSTR 144
#define SMEM_BYTES (2*HH*ZSTR*4)

// ---------------- scratch (static device globals; no allocation) ----------------
__device__ float g_F2r[WW*NROW];         // after T+H DFT, W-MAJOR: (w, bc*128+kt*16+kx)
__device__ float g_F2i[WW*NROW];
__device__ float g_F3r[BC*NMODE];        // after W-DFT: (bc, m)  m = kt*256+kx*16+ky
__device__ float g_F3i[BC*NMODE];
__device__ float g_Sr [BD*NMODE];        // after mix:   (bd, m)
__device__ float g_Si [BD*NMODE];

// ---------------- compile-time trig (Taylor, double precision) ----------------
__host__ __device__ constexpr double ct_cos(double x) {
    double x2 = x * x, t = 1.0, s = 1.0;
    for (int k = 1; k <= 26; k++) { t *= -x2 / ((2.0*k - 1.0) * (2.0*k)); s += t; }
    return s;
}
__host__ __device__ constexpr double ct_sin(double x) {
    double x2 = x * x, t = x, s = x;
    for (int k = 1; k <= 26; k++) { t *= -x2 / ((2.0*k) * (2.0*k + 1.0)); s += t; }
    return s;
}

// Twiddle cos/sin(2*pi*P/N) with exact 0 / +-1 at quadrant points
template<int P, int N> struct TW {
    static constexpr int    q0 = ((P % N) + N) % N;
    static constexpr int    aq = (q0 > N - q0) ? (N - q0) : q0;
    static constexpr int    ss = (q0 > N/2) ? -1 : 1;
    static constexpr bool c_zero = (4*aq == N);
    static constexpr bool s_zero = (aq == 0) || (2*aq == N);
    static constexpr float c =
        (aq == 0)     ? 1.0f  :
        (2*aq == N)   ? -1.0f :
        c_zero        ? 0.0f  :
        (float)ct_cos(6.283185307179586476925286766559 * (double)aq / (double)N);
    static constexpr float s =
        s_zero        ? 0.0f :
        (4*aq == N)   ? (ss > 0 ? 1.0f : -1.0f) :
        (float)(ss * ct_sin(6.283185307179586476925286766559 * (double)aq / (double)N));
};

template<int P, int N, int SG = 1>
__device__ __forceinline__ float fC(float v, float acc) {
    using T = TW<P, N>;
    constexpr float cc = (SG < 0) ? -T::c : T::c;
    if constexpr (T::c_zero)         return acc;
    else if constexpr (cc ==  1.0f)  return acc + v;
    else if constexpr (cc == -1.0f)  return acc - v;
    else                             return fmaf(v, cc, acc);
}
template<int P, int N, int SG = 1>
__device__ __forceinline__ float fS(float v, float acc) {
    using T = TW<P, N>;
    constexpr float sv = (SG < 0) ? -T::s : T::s;
    if constexpr (T::s_zero)         return acc;
    else if constexpr (sv ==  1.0f)  return acc + v;
    else if constexpr (sv == -1.0f)  return acc - v;
    else                             return fmaf(v, sv, acc);
}

// ---------------- compile-time unroller ----------------
template<int I> struct Ic { static constexpr int v = I; };
template<int I, int E, class F> __device__ __forceinline__ void UNR(F&& f) {
    if constexpr (I < E) { f(Ic<I>{}); UNR<I+1, E>(f); }
}

// ---------------- KA: fused T-DFT + H-DFT  (x -> F2, w-major), w-tile 16, 256 thr ----------------
// smem Y layout: [h][kt*16 + wl], row stride ZSTR
__global__ void __maxnreg__(112) kA_fwd(const float* __restrict__ x) {
    extern __shared__ float sm[];
    float* Yr = sm;                     // HH*ZSTR floats
    float* Yi = sm + HH*ZSTR;
    const int tid = threadIdx.x;
    const int bc = blockIdx.x / 6;
    const int w0 = (blockIdx.x % 6) * 16;
    const float* xb = x + (size_t)bc * TT * HW + w0;

    const int wl = tid & 15;

    // phase1: T-DFT (real -> complex), folded over t <-> 32-t. 16 hs x 6 passes.
    {
        const int hs = tid >> 4;            // 0..15
        for (int p = 0; p < 6; p++) {
            const int h = p * 16 + hs;
            const float* xp = xb + h * WW + wl;
            float ar[MT], ai[MT];
            float x0  = xp[0];
            float x16 = xp[16 * HW];
            UNR<0,MT>([&](auto K){ constexpr int k = decltype(K)::v;
                ar[k] = (k & 1) ? (x0 - x16) : (x0 + x16);
                ai[k] = 0.0f; });
            UNR<1,16>([&](auto T){ constexpr int t = decltype(T)::v;
                float a = xp[(size_t)t * HW];
                float b = xp[(size_t)(TT - t) * HW];
                float pt = a + b, mt = a - b;
                UNR<0,MT>([&](auto K){ constexpr int k = decltype(K)::v;
                    ar[k] = fC<t*k, TT>(pt, ar[k]);
                    ai[k] = fS<t*k, TT, -1>(mt, ai[k]);
                });
            });
            UNR<0,MT>([&](auto K){ constexpr int k = decltype(K)::v;
                Yr[h*ZSTR + k*16 + wl] = ar[k];
                Yi[h*ZSTR + k*16 + wl] = ai[k]; });
        }
    }
    __syncthreads();

    // phase2: H-DFT (complex), folded over h <-> 96-h. kx split in two halves.
    {
        const int kt   = (tid >> 4) & 7;
        const int half = tid >> 7;
        const float* yr = Yr + kt*16 + wl;
        const float* yi = Yi + kt*16 + wl;
        auto run = [&](auto K0C){
            constexpr int K0 = decltype(K0C)::v;
            float fr[8], fi[8];
            float a0  = yr[0],       b0  = yi[0];
            float a48 = yr[48*ZSTR], b48 = yi[48*ZSTR];
            UNR<0,8>([&](auto J){ constexpr int j = decltype(J)::v; constexpr int kx = K0 + j;
                fr[j] = (kx & 1) ? (a0 - a48) : (a0 + a48);
                fi[j] = (kx & 1) ? (b0 - b48) : (b0 + b48); });
            UNR<1,48>([&](auto H){ constexpr int h = decltype(H)::v;
                float a  = yr[h*ZSTR],      b  = yi[h*ZSTR];
                float a2 = yr[(96-h)*ZSTR], b2 = yi[(96-h)*ZSTR];
                float pa = a + a2, ma = a - a2, pb = b + b2, mb = b - b2;
                UNR<0,8>([&](auto J){ constexpr int j = decltype(J)::v; constexpr int kx = K0 + j;
                    fr[j] = fC<h*kx, HH>(pa, fS<h*kx, HH>(mb, fr[j]));
                    fi[j] = fC<h*kx, HH>(pb, fS<h*kx, HH, -1>(ma, fi[j]));
                });
            });
            size_t base = (size_t)(w0 + wl) * NROW + bc*128 + kt*16 + K0;
            UNR<0,8>([&](auto J){ constexpr int j = decltype(J)::v;
                g_F2r[base + j] = fr[j];
                g_F2i[base + j] = fi[j]; });
        };
        if (half == 0) run(Ic<0>{}); else run(Ic<8>{});
    }
}

// ---------------- K3: W-DFT (F2 -> F3), coalesced, folded over w <-> 96-w ----------------
__global__ void __launch_bounds__(128) k3_wdft() {
    int r = blockIdx.x * 128 + threadIdx.x;       // 32768 rows, exact
    const float* pr = g_F2r + r;
    const float* pi = g_F2i + r;
    float fr[MS], fi[MS];
    {
        float a0  = pr[0],                  b0  = pi[0];
        float a48 = pr[(size_t)48 * NROW],  b48 = pi[(size_t)48 * NROW];
        UNR<0,MS>([&](auto K){ constexpr int ky = decltype(K)::v;
            fr[ky] = (ky & 1) ? (a0 - a48) : (a0 + a48);
            fi[ky] = (ky & 1) ? (b0 - b48) : (b0 + b48); });
    }
    UNR<1,48>([&](auto WI){ constexpr int w = decltype(WI)::v;
        float a  = pr[(size_t)w * NROW],      b  = pi[(size_t)w * NROW];
        float a2 = pr[(size_t)(96-w) * NROW], b2 = pi[(size_t)(96-w) * NROW];
        float pa = a + a2, ma = a - a2, pb = b + b2, mb = b - b2;
        UNR<0,MS>([&](auto K){ constexpr int ky = decltype(K)::v;
            fr[ky] = fC<w*ky, WW>(pa, fS<w*ky, WW>(mb, fr[ky]));
            fi[ky] = fC<w*ky, WW>(pb, fS<w*ky, WW, -1>(ma, fi[ky]));
        });
    });
    size_t o = (size_t)r * MS;
    UNR<0,MS>([&](auto K){ constexpr int ky = decltype(K)::v;
        g_F3r[o + ky] = fr[ky];
        g_F3i[o + ky] = fi[ky]; });
}

// ---------------- K4: channel mix, weights read in ORIGINAL layout ----------------
// Full c-unroll so ptxas front-batches the 64 weight loads (MLP).
__global__ void __launch_bounds__(256) k4_mix(const float* __restrict__ wr,
                                              const float* __restrict__ wi) {
    __shared__ float Xr[BC*8], Xi[BC*8];         // 16 KB
    const int m0 = blockIdx.x * 8;
    const int tid = threadIdx.x;
    for (int i = tid; i < BC*8; i += 256) {
        int bcc = i >> 3, mm = i & 7;
        Xr[i] = g_F3r[(size_t)bcc * NMODE + m0 + mm];
        Xi[i] = g_F3i[(size_t)bcc * NMODE + m0 + mm];
    }
    __syncthreads();
    const int d  = tid >> 3;
    const int ml = tid & 7;
    const int m  = m0 + ml;
    const float* wrp = wr + (size_t)d * NMODE + m;
    const float* wip = wi + (size_t)d * NMODE + m;

    float sr[BB], si[BB];
#pragma unroll
    for (int b = 0; b < BB; b++) { sr[b] = 0.0f; si[b] = 0.0f; }

#pragma unroll
    for (int c = 0; c < CC; c++) {
        float a  = wrp[(size_t)c * DD * NMODE];
        float bb = wip[(size_t)c * DD * NMODE];
#pragma unroll
        for (int b = 0; b < BB; b++) {
            float xr = Xr[(b*CC + c)*8 + ml];
            float xi = Xi[(b*CC + c)*8 + ml];
            sr[b] = fmaf(xr, a,  fmaf(-xi, bb, sr[b]));
            si[b] = fmaf(xr, bb, fmaf( xi, a,  si[b]));
        }
    }
    float sc = (((m & (MS-1)) == 0) ? 1.0f : 2.0f) * (1.0f / 294912.0f);
#pragma unroll
    for (int b = 0; b < BB; b++) {
        size_t o = (size_t)(b*DD + d) * NMODE + m;
        g_Sr[o] = sr[b] * sc;
        g_Si[o] = si[b] * sc;
    }
}

// ---------------- KB: fused W-exp + H-exp + T-exp  (S -> out), w-tile 16, 256 thr ----------------
// phase0 keeps a1[16] in registers (redundant across halves) -> no a1 smem.
// smem: Z only = 110592 B; regs capped 112 -> 2 CTAs/SM.
__global__ void __maxnreg__(112) kB_inv(float* __restrict__ out) {
    extern __shared__ float sm[];
    float* Zr  = sm;                             // HH*ZSTR floats
    float* Zi  = sm + HH*ZSTR;
    float*  Ssr = sm;                            // phase0 staging aliases Z
    float*  Ssi = sm + 2048;
    float2* tab = reinterpret_cast<float2*>(sm + 4096);   // [ky][wl] 256 float2

    const int tid = threadIdx.x;
    const int bd = blockIdx.x / 6;
    const int w0 = (blockIdx.x % 6) * 16;
    const int wl = tid & 15;
    const int kt = (tid >> 4) & 7;
    const int half = tid >> 7;

    {   // load S tile (coalesced) + per-block w table
        const float* srp = g_Sr + (size_t)bd * NMODE;
        const float* sip = g_Si + (size_t)bd * NMODE;
        for (int i = tid; i < NMODE; i += 256) { Ssr[i] = srp[i]; Ssi[i] = sip[i]; }
        {
            int ky = tid >> 4, wl2 = tid & 15;
            float ssin, ccos;
            sincosf(TWO_PI * (float)((ky * (w0 + wl2)) % WW) / (float)WW, &ssin, &ccos);
            tab[tid] = make_float2(ccos, ssin);
        }
    }
    __syncthreads();

    // phase0: W-expand into registers, all 16 kx per thread, e^{+i 2pi ky w / 96}
    float a1r[MS], a1i[MS];
    {
        float ec[MS], es[MS];
#pragma unroll
        for (int ky = 0; ky < MS; ky++) { float2 e = tab[ky*16 + wl]; ec[ky] = e.x; es[ky] = e.y; }
#pragma unroll
        for (int kx = 0; kx < MS; kx++) {
            const float* pr = Ssr + (kt*MS + kx) * MS;
            const float* pi = Ssi + (kt*MS + kx) * MS;
            float rr = 0.f, ii = 0.f;
#pragma unroll
            for (int ky = 0; ky < MS; ky++) {
                float sv = pr[ky], iv = pi[ky];
                rr = fmaf(sv, ec[ky], fmaf(-iv, es[ky], rr));
                ii = fmaf(sv, es[ky], fmaf( iv, ec[ky], ii));
            }
            a1r[kx] = rr; a1i[kx] = ii;
        }
    }
    __syncthreads();   // staging reads done before Z overwrites

    // phase1: H-expand, folded over output h <-> 96-h; halves split the h range
    {
        auto body = [&](auto H){ constexpr int h = decltype(H)::v;
            float C = 0.f, S = 0.f, C2 = 0.f, S2 = 0.f;
            UNR<0,MS>([&](auto KX){ constexpr int kx = decltype(KX)::v;
                C  = fC<kx*h, HH>(a1r[kx], C);
                C2 = fC<kx*h, HH>(a1i[kx], C2);
                S  = fS<kx*h, HH>(a1i[kx], S);
                S2 = fS<kx*h, HH>(a1r[kx], S2);
            });
            Zr[h*ZSTR + kt*16 + wl] = C - S;
            Zi[h*ZSTR + kt*16 + wl] = C2 + S2;
            if constexpr (h >= 1 && h <= 47) {
                Zr[(96-h)*ZSTR + kt*16 + wl] = C + S;
                Zi[(96-h)*ZSTR + kt*16 + wl] = C2 - S2;
            }
        };
        if (half == 0) UNR<0,25>(body); else UNR<25,49>(body);
    }
    __syncthreads();

    // phase2: T-expand + real part, folded over output t <-> 32-t. 16 hs x 6 passes.
    float* ob = out + (size_t)bd * TT * HW + w0;
    const int hs = tid >> 4;            // 0..15
    for (int p = 0; p < 6; p++) {
        const int h = p * 16 + hs;
        float zr[MT], zi[MT];
        UNR<0,MT>([&](auto K){ constexpr int k = decltype(K)::v;
            zr[k] = Zr[h*ZSTR + k*16 + wl];
            zi[k] = Zi[h*ZSTR + k*16 + wl]; });
        float* op = ob + h * WW + wl;
        {   // t = 0 and t = 16
            float s0 = 0.f, s16 = 0.f;
            UNR<0,MT>([&](auto K){ constexpr int k = decltype(K)::v;
                s0 += zr[k];
                s16 = (k & 1) ? (s16 - zr[k]) : (s16 + zr[k]); });
            op[0] = s0;
            op[(size_t)16 * HW] = s16;
        }
        UNR<1,16>([&](auto T){ constexpr int t = decltype(T)::v;
            float C = 0.f, S = 0.f;
            UNR<0,MT>([&](auto K){ constexpr int k = decltype(K)::v;
                C = fC<k*t, TT>(zr[k], C);
                S = fS<k*t, TT>(zi[k], S);
            });
            op[(size_t)t * HW]        = C - S;
            op[(size_t)(32 - t) * HW] = C + S;
        });
    }
}

// ---------------- launch ----------------
extern "C" void kernel_launch(void* const* d_in, const int* in_sizes, int n_in,
                              void* d_out, int out_size) {
    (void)in_sizes; (void)n_in; (void)out_size;
    const float* x  = (const float*)d_in[0];
    const float* wr = (const float*)d_in[1];
    const float* wi = (const float*)d_in[2];
    float* out = (float*)d_out;

    cudaFuncSetAttribute(kA_fwd, cudaFuncAttributeMaxDynamicSharedMemorySize, SMEM_BYTES);
    cudaFuncSetAttribute(kB_inv, cudaFuncAttributeMaxDynamicSharedMemorySize, SMEM_BYTES);

    kA_fwd <<<1536, 256, SMEM_BYTES>>>(x);    // 256 bc * 6 w-groups
    k3_wdft<<<256,  128>>>();                 // 32768 rows
    k4_mix <<<256,  256>>>(wr, wi);           // 2048 modes / 8 per block
    kB_inv <<<1536, 256, SMEM_BYTES>>>(out);  // 256 bd * 6 w-groups
}